// round 1
// baseline (speedup 1.0000x reference)
#include <cuda_runtime.h>

#define NN 50000
#define FF 64
#define EE 800000

// Scratch (static __device__ — no allocations allowed)
__device__ float g_q[(size_t)NN * 128];      // [N][h*64+f]  (heads concatenated)
__device__ float g_k[(size_t)NN * 128];
__device__ float g_ex[(size_t)EE * 2];       // exp(s) per edge per head
__device__ float g_denom[NN * 2];            // per-row per-head softmax denominator

__global__ void zero_denom_kernel() {
    int i = blockIdx.x * blockDim.x + threadIdx.x;
    if (i < NN * 2) g_denom[i] = 0.0f;
}

// GEMM: qk = x @ W + b, split into q/k tables with head-contiguous layout.
// One thread per output column (256 cols). W column held in 64 registers.
// 32 rows of x staged in smem, read back as float4 broadcast.
__global__ void __launch_bounds__(256) gemm_qk_kernel(const float* __restrict__ x,
                                                      const float* __restrict__ W,
                                                      const float* __restrict__ b) {
    __shared__ float xs[32 * 64];
    const int c  = threadIdx.x;       // output column 0..255
    const int n0 = blockIdx.x * 32;

    float wreg[64];
#pragma unroll
    for (int k = 0; k < 64; k++) wreg[k] = __ldg(W + k * 256 + c);
    const float bc = __ldg(b + c);

    // cooperative x-tile load (2048 floats, 8 per thread, coalesced)
#pragma unroll
    for (int i = 0; i < 8; i++) {
        int lin = c + i * 256;
        int r = lin >> 6, kk = lin & 63;
        int n = n0 + r;
        xs[lin] = (n < NN) ? x[(size_t)n * 64 + kk] : 0.0f;
    }
    __syncthreads();

    // column -> (head, q/k, feat):  col = h*128 + s*64 + f
    const int h = c >> 7;
    const int sflag = (c >> 6) & 1;
    const int f = c & 63;
    float* outbase = sflag ? g_k : g_q;

    const int rows = (NN - n0 < 32) ? (NN - n0) : 32;
    const float4* xs4 = (const float4*)xs;
    for (int r = 0; r < rows; r++) {
        float acc = bc;
#pragma unroll
        for (int k4 = 0; k4 < 16; k4++) {
            float4 xv = xs4[r * 16 + k4];
            acc = fmaf(xv.x, wreg[4 * k4 + 0], acc);
            acc = fmaf(xv.y, wreg[4 * k4 + 1], acc);
            acc = fmaf(xv.z, wreg[4 * k4 + 2], acc);
            acc = fmaf(xv.w, wreg[4 * k4 + 3], acc);
        }
        outbase[(size_t)(n0 + r) * 128 + h * 64 + f] = acc;
    }
}

// One warp per edge. Lane l reads float4 of q[row] and k[col] (128 floats each,
// covers both heads: lanes 0-15 -> head 0, 16-31 -> head 1). 16-lane shuffle
// reduce, then exp + atomicAdd into the row's denominator. No max pass:
// |s| <~ 15 here, exp() is safely inside fp32 range and the softmax ratio is
// algebraically identical to the max-subtracted form.
__global__ void __launch_bounds__(256) edge_scores_kernel(const int* __restrict__ row,
                                                          const int* __restrict__ col) {
    int gwarp = (blockIdx.x * 256 + threadIdx.x) >> 5;
    int lane = threadIdx.x & 31;
    if (gwarp >= EE) return;

    int r  = __ldg(row + gwarp);
    int cc = __ldg(col + gwarp);

    float4 qv = *(const float4*)(g_q + (size_t)r  * 128 + lane * 4);
    float4 kv = *(const float4*)(g_k + (size_t)cc * 128 + lane * 4);
    float p = qv.x * kv.x + qv.y * kv.y + qv.z * kv.z + qv.w * kv.w;

    p += __shfl_xor_sync(0xffffffffu, p, 8);
    p += __shfl_xor_sync(0xffffffffu, p, 4);
    p += __shfl_xor_sync(0xffffffffu, p, 2);
    p += __shfl_xor_sync(0xffffffffu, p, 1);

    if ((lane & 15) == 0) {
        int h = lane >> 4;
        float e = __expf(p);
        g_ex[(size_t)gwarp * 2 + h] = e;
        atomicAdd(g_denom + r * 2 + h, e);
    }
}

__global__ void __launch_bounds__(256) finalize_kernel(const int* __restrict__ row,
                                                       float* __restrict__ out) {
    int e = blockIdx.x * blockDim.x + threadIdx.x;
    if (e >= EE) return;
    int r = row[e];
    float ex0 = g_ex[2 * (size_t)e], ex1 = g_ex[2 * (size_t)e + 1];
    float d0 = g_denom[2 * r], d1 = g_denom[2 * r + 1];
    out[e] = 0.5f * (ex0 / d0 + ex1 / d1);
}

extern "C" void kernel_launch(void* const* d_in, const int* in_sizes, int n_in,
                              void* d_out, int out_size) {
    const float* x    = (const float*)d_in[0];
    const float* W_qk = (const float*)d_in[1];
    const float* b_qk = (const float*)d_in[2];
    const int*   ei   = (const int*)d_in[3];   // [2, E] row-major
    const int* row = ei;
    const int* col = ei + EE;
    float* out = (float*)d_out;

    zero_denom_kernel<<<(NN * 2 + 255) / 256, 256>>>();
    gemm_qk_kernel<<<(NN + 31) / 32, 256>>>(x, W_qk, b_qk);
    edge_scores_kernel<<<(EE * 32 + 255) / 256, 256>>>(row, col);
    finalize_kernel<<<(EE + 255) / 256, 256>>>(row, out);
}

// round 2
// speedup vs baseline: 1.2009x; 1.2009x over previous
#include <cuda_runtime.h>

#define NN 50000
#define FF 64
#define EE 800000
#define SCAN_BLOCKS ((NN + 255) / 256)   // 196

// Scratch (static __device__ — no allocations allowed)
__device__ float g_q[(size_t)NN * 128];      // [N][h*64+f]
__device__ float g_k[(size_t)NN * 128];
__device__ int   g_hist[NN];
__device__ int   g_start[NN + 1];
__device__ int   g_bsum[256];
__device__ int   g_cursor[NN];
__device__ int   g_scol[EE];                 // col ids in row-sorted order
__device__ int   g_perm[EE];                 // original edge id per sorted pos
__device__ float g_ex2[(size_t)EE * 2];      // exp(s) per sorted pos per head

// ---------------- counting sort of edges by row ----------------

__global__ void zero_hist_kernel() {
    int i = blockIdx.x * blockDim.x + threadIdx.x;
    if (i < NN) g_hist[i] = 0;
}

__global__ void hist_kernel(const int* __restrict__ row) {
    int e = blockIdx.x * blockDim.x + threadIdx.x;
    if (e < EE) atomicAdd(&g_hist[row[e]], 1);
}

__global__ void scan1_kernel() {
    __shared__ int sh[256];
    int t = threadIdx.x;
    int i = blockIdx.x * 256 + t;
    int v = (i < NN) ? g_hist[i] : 0;
    sh[t] = v;
    __syncthreads();
#pragma unroll
    for (int off = 1; off < 256; off <<= 1) {
        int u = (t >= off) ? sh[t - off] : 0;
        __syncthreads();
        sh[t] += u;
        __syncthreads();
    }
    if (i < NN) g_start[i] = sh[t] - v;          // exclusive within block
    if (t == 255) g_bsum[blockIdx.x] = sh[t];    // block total
}

__global__ void scan2_kernel() {   // single block: exclusive scan of block sums
    __shared__ int sh[256];
    int t = threadIdx.x;
    int v = (t < SCAN_BLOCKS) ? g_bsum[t] : 0;
    sh[t] = v;
    __syncthreads();
#pragma unroll
    for (int off = 1; off < 256; off <<= 1) {
        int u = (t >= off) ? sh[t - off] : 0;
        __syncthreads();
        sh[t] += u;
        __syncthreads();
    }
    g_bsum[t] = sh[t] - v;   // exclusive
}

__global__ void scan3_kernel() {
    int i = blockIdx.x * blockDim.x + threadIdx.x;
    if (i < NN) {
        int s = g_start[i] + g_bsum[i >> 8];
        g_start[i] = s;
        g_cursor[i] = s;
    }
    if (i == 0) g_start[NN] = EE;
}

__global__ void scatter_kernel(const int* __restrict__ row, const int* __restrict__ col) {
    int e = blockIdx.x * blockDim.x + threadIdx.x;
    if (e >= EE) return;
    int r = row[e];
    int pos = atomicAdd(&g_cursor[r], 1);
    g_scol[pos] = col[e];
    g_perm[pos] = e;
}

// ---------------- QK projection GEMM ----------------
// One thread per output column (256 cols). W column in 64 regs; 32-row x tile
// in smem read back as float4 broadcast.
__global__ void __launch_bounds__(256) gemm_qk_kernel(const float* __restrict__ x,
                                                      const float* __restrict__ W,
                                                      const float* __restrict__ b) {
    __shared__ float xs[32 * 64];
    const int c  = threadIdx.x;
    const int n0 = blockIdx.x * 32;

    float wreg[64];
#pragma unroll
    for (int k = 0; k < 64; k++) wreg[k] = __ldg(W + k * 256 + c);
    const float bc = __ldg(b + c);

#pragma unroll
    for (int i = 0; i < 8; i++) {
        int lin = c + i * 256;
        int r = lin >> 6, kk = lin & 63;
        int n = n0 + r;
        xs[lin] = (n < NN) ? x[(size_t)n * 64 + kk] : 0.0f;
    }
    __syncthreads();

    const int h = c >> 7;
    const int sflag = (c >> 6) & 1;
    const int f = c & 63;
    float* outbase = sflag ? g_k : g_q;

    const int rows = (NN - n0 < 32) ? (NN - n0) : 32;
    const float4* xs4 = (const float4*)xs;
    for (int r = 0; r < rows; r++) {
        float acc = bc;
#pragma unroll
        for (int k4 = 0; k4 < 16; k4++) {
            float4 xv = xs4[r * 16 + k4];
            acc = fmaf(xv.x, wreg[4 * k4 + 0], acc);
            acc = fmaf(xv.y, wreg[4 * k4 + 1], acc);
            acc = fmaf(xv.z, wreg[4 * k4 + 2], acc);
            acc = fmaf(xv.w, wreg[4 * k4 + 3], acc);
        }
        outbase[(size_t)(n0 + r) * 128 + h * 64 + f] = acc;
    }
}

// ---------------- fused edge scores + softmax + output ----------------
// One warp per row. q[row] loaded once into registers; loop over the row's
// sorted edges gathering only k[col] (512 B each), 2-way unrolled for MLP=2.
// Denominators accumulate in registers (lanes 0 & 16), then a second warp-wide
// loop normalizes and scatter-writes out[perm[pos]].
__global__ void __launch_bounds__(256) edge_row_kernel(float* __restrict__ out) {
    int r = (blockIdx.x * 256 + threadIdx.x) >> 5;
    int lane = threadIdx.x & 31;
    if (r >= NN) return;

    int s0 = g_start[r];
    int s1 = g_start[r + 1];
    if (s0 == s1) return;

    float4 qv = *(const float4*)(g_q + (size_t)r * 128 + lane * 4);

    float d = 0.0f;   // head-denominator partial (valid on lanes 0 and 16)
    const bool head_lane = ((lane & 15) == 0);

    for (int pos = s0; pos < s1; pos += 2) {
        int c0 = g_scol[pos];
        bool has2 = (pos + 1 < s1);
        int c1 = has2 ? g_scol[pos + 1] : c0;

        float4 k0 = __ldg((const float4*)(g_k + (size_t)c0 * 128 + lane * 4));
        float4 k1 = __ldg((const float4*)(g_k + (size_t)c1 * 128 + lane * 4));

        float p0 = qv.x * k0.x + qv.y * k0.y + qv.z * k0.z + qv.w * k0.w;
        float p1 = qv.x * k1.x + qv.y * k1.y + qv.z * k1.z + qv.w * k1.w;

#pragma unroll
        for (int off = 8; off >= 1; off >>= 1) {
            p0 += __shfl_xor_sync(0xffffffffu, p0, off);
            p1 += __shfl_xor_sync(0xffffffffu, p1, off);
        }

        if (head_lane) {
            int h = lane >> 4;
            float e0 = __expf(p0);
            g_ex2[2 * (size_t)pos + h] = e0;
            d += e0;
            if (has2) {
                float e1 = __expf(p1);
                g_ex2[2 * (size_t)(pos + 1) + h] = e1;
                d += e1;
            }
        }
    }

    float D0 = __shfl_sync(0xffffffffu, d, 0);
    float D1 = __shfl_sync(0xffffffffu, d, 16);
    float inv0 = 0.5f / D0, inv1 = 0.5f / D1;
    __syncwarp();

    for (int pos = s0 + lane; pos < s1; pos += 32) {
        float2 e = *(const float2*)(g_ex2 + 2 * (size_t)pos);
        out[g_perm[pos]] = e.x * inv0 + e.y * inv1;
    }
}

extern "C" void kernel_launch(void* const* d_in, const int* in_sizes, int n_in,
                              void* d_out, int out_size) {
    const float* x    = (const float*)d_in[0];
    const float* W_qk = (const float*)d_in[1];
    const float* b_qk = (const float*)d_in[2];
    const int*   ei   = (const int*)d_in[3];   // [2, E] row-major
    const int* row = ei;
    const int* col = ei + EE;
    float* out = (float*)d_out;

    zero_hist_kernel<<<SCAN_BLOCKS, 256>>>();
    hist_kernel<<<(EE + 255) / 256, 256>>>(row);
    scan1_kernel<<<SCAN_BLOCKS, 256>>>();
    scan2_kernel<<<1, 256>>>();
    scan3_kernel<<<SCAN_BLOCKS, 256>>>();
    scatter_kernel<<<(EE + 255) / 256, 256>>>(row, col);
    gemm_qk_kernel<<<(NN + 31) / 32, 256>>>(x, W_qk, b_qk);
    edge_row_kernel<<<(NN * 32 + 255) / 256, 256>>>(out);
}

// round 3
// speedup vs baseline: 1.2288x; 1.0233x over previous
#include <cuda_runtime.h>

#define NN 50000
#define FF 64
#define EE 800000
#define SCAN_BLOCKS ((NN + 255) / 256)   // 196
#define EX_CAP 128

// Scratch (static __device__ — no allocations allowed; zero-initialized at load)
__device__ float g_q[(size_t)NN * 128];      // [N][h*64+f]
__device__ float g_k[(size_t)NN * 128];
__device__ int   g_hist[NN];
__device__ int   g_start[NN + 1];
__device__ int   g_bsum[256];
__device__ int   g_cursor[NN];
__device__ int2  g_sedge[EE];                // (col, orig edge id) in row-sorted order
__device__ float g_ex2[(size_t)EE * 2];      // fallback exp storage (deg > EX_CAP)

// f32x2 packed-math helpers (Blackwell FFMA2 path — only reachable via PTX)
#define FMA_F32X2(d, a, b, c) \
    asm("fma.rn.f32x2 %0, %1, %2, %3;" : "=l"(d) : "l"(a), "l"(b), "l"(c))
#define ADD_F32X2(d, a, b) \
    asm("add.rn.f32x2 %0, %1, %2;" : "=l"(d) : "l"(a), "l"(b))
#define PACK_F32X2(d, lo, hi) \
    asm("mov.b64 %0, {%1, %2};" : "=l"(d) : "f"(lo), "f"(hi))
#define UNPACK_F32X2(lo, hi, s) \
    asm("mov.b64 {%0, %1}, %2;" : "=f"(lo), "=f"(hi) : "l"(s))

// ---------------- counting sort of edges by row ----------------

__global__ void hist_kernel(const int4* __restrict__ row4) {
    int i = blockIdx.x * blockDim.x + threadIdx.x;
    if (i < EE / 4) {
        int4 r = __ldg(row4 + i);
        atomicAdd(&g_hist[r.x], 1);
        atomicAdd(&g_hist[r.y], 1);
        atomicAdd(&g_hist[r.z], 1);
        atomicAdd(&g_hist[r.w], 1);
    }
}

// Within-block exclusive scan of hist; also RESETS g_hist to 0 for the next
// graph replay (globals start zeroed at load, so every execution sees zeros).
__global__ void scan1_kernel() {
    __shared__ int sh[256];
    int t = threadIdx.x;
    int i = blockIdx.x * 256 + t;
    int v = 0;
    if (i < NN) { v = g_hist[i]; g_hist[i] = 0; }
    sh[t] = v;
    __syncthreads();
#pragma unroll
    for (int off = 1; off < 256; off <<= 1) {
        int u = (t >= off) ? sh[t - off] : 0;
        __syncthreads();
        sh[t] += u;
        __syncthreads();
    }
    if (i < NN) g_start[i] = sh[t] - v;
    if (t == 255) g_bsum[blockIdx.x] = sh[t];
}

// Each block computes its own exclusive prefix over block sums (196 ints) and
// finalizes g_start / g_cursor. Replaces the old scan2+scan3 pair.
__global__ void scan3b_kernel() {
    __shared__ int sh[256];
    int t = threadIdx.x;
    int bid = blockIdx.x;
    sh[t] = (t < bid && t < SCAN_BLOCKS) ? g_bsum[t] : 0;
    __syncthreads();
#pragma unroll
    for (int off = 128; off >= 1; off >>= 1) {
        if (t < off) sh[t] += sh[t + off];
        __syncthreads();
    }
    int base = sh[0];
    int i = bid * 256 + t;
    if (i < NN) {
        int s = g_start[i] + base;
        g_start[i] = s;
        g_cursor[i] = s;
    }
    if (i == 0) g_start[NN] = EE;
}

__global__ void scatter_kernel(const int* __restrict__ row, const int* __restrict__ col) {
    int e = blockIdx.x * blockDim.x + threadIdx.x;
    if (e >= EE) return;
    int r = row[e];
    int pos = atomicAdd(&g_cursor[r], 1);
    g_sedge[pos] = make_int2(col[e], e);
}

// ---------------- QK projection GEMM (f32x2 / FFMA2) ----------------
// 64 rows x 256 cols per block. x tile staged in smem as duplicated (x,x)
// float2 pairs so the inner loop is LDS.128 + fma.rn.f32x2 only.
// Thread owns columns (c, c+128) [same (q/k, feat), two heads] over 32 rows.
__global__ void __launch_bounds__(256, 1) gemm_qk_kernel(const float* __restrict__ x,
                                                         const float* __restrict__ W,
                                                         const float* __restrict__ b) {
    __shared__ float2 xs[64 * 64];   // [row][k] duplicated pairs, 32KB
    const int tid = threadIdx.x;
    const int n0 = blockIdx.x * 64;

    // stage: 64 rows x 64 floats = 1024 float4, 4 per thread
#pragma unroll
    for (int i = 0; i < 4; i++) {
        int lin = tid + i * 256;          // float4 index
        int r = lin >> 4, k4 = lin & 15;
        int n = n0 + r;
        float4 v = make_float4(0.f, 0.f, 0.f, 0.f);
        if (n < NN) v = __ldg((const float4*)x + (size_t)n * 16 + k4);
        float2* dst = &xs[r * 64 + k4 * 4];
        dst[0] = make_float2(v.x, v.x);
        dst[1] = make_float2(v.y, v.y);
        dst[2] = make_float2(v.z, v.z);
        dst[3] = make_float2(v.w, v.w);
    }

    const int c = tid & 127;              // column pair (c, c+128)
    const int rbase = (tid >> 7) * 32;    // rows [rbase, rbase+32)

    unsigned long long wp[64];
#pragma unroll
    for (int k = 0; k < 64; k++) {
        float w0 = __ldg(W + k * 256 + c);
        float w1 = __ldg(W + k * 256 + c + 128);
        PACK_F32X2(wp[k], w0, w1);
    }
    const float b0 = __ldg(b + c);
    const float b1 = __ldg(b + c + 128);

    __syncthreads();

    const int sflag = (c >> 6) & 1;       // 0 -> q table, 1 -> k table
    const int f = c & 63;
    float* outbase = sflag ? g_k : g_q;

    for (int r = rbase; r < rbase + 32; r++) {
        int n = n0 + r;
        if (n >= NN) break;
        unsigned long long acc_a, acc_b, zero_p;
        PACK_F32X2(acc_a, b0, b1);
        PACK_F32X2(zero_p, 0.0f, 0.0f);
        acc_b = zero_p;
        const ulonglong2* xr = (const ulonglong2*)&xs[r * 64];
#pragma unroll
        for (int j = 0; j < 32; j++) {
            ulonglong2 xv = xr[j];        // dup pairs for k=2j, 2j+1
            FMA_F32X2(acc_a, xv.x, wp[2 * j], acc_a);
            FMA_F32X2(acc_b, xv.y, wp[2 * j + 1], acc_b);
        }
        unsigned long long acc;
        ADD_F32X2(acc, acc_a, acc_b);
        float o0, o1;
        UNPACK_F32X2(o0, o1, acc);
        outbase[(size_t)n * 128 + f] = o0;        // head 0
        outbase[(size_t)n * 128 + 64 + f] = o1;   // head 1
    }
}

// ---------------- fused edge scores + softmax + output ----------------
// One warp per row; q in registers; 4-wide unrolled k gather (MLP=4);
// exp values buffered in shared memory (global fallback for deg > EX_CAP).
__global__ void __launch_bounds__(256) edge_row_kernel(float* __restrict__ out) {
    __shared__ float2 exs[8][EX_CAP + 4];
    const int warp = threadIdx.x >> 5;
    const int lane = threadIdx.x & 31;
    const int r = blockIdx.x * 8 + warp;
    if (r >= NN) return;

    const int s0 = g_start[r];
    const int s1 = g_start[r + 1];
    const int deg = s1 - s0;
    if (deg == 0) return;

    const float4 qv = *(const float4*)(g_q + (size_t)r * 128 + lane * 4);
    const float4* kp = (const float4*)g_k;
    const bool head_lane = ((lane & 15) == 0);
    const int h = lane >> 4;
    float d = 0.0f;

    if (deg <= EX_CAP) {
        int pos = s0;
        const int qend = s0 + (deg & ~3);
        for (; pos < qend; pos += 4) {
            int2 e0 = g_sedge[pos],     e1 = g_sedge[pos + 1];
            int2 e2 = g_sedge[pos + 2], e3 = g_sedge[pos + 3];
            float4 k0 = __ldg(kp + e0.x * 32 + lane);
            float4 k1 = __ldg(kp + e1.x * 32 + lane);
            float4 k2 = __ldg(kp + e2.x * 32 + lane);
            float4 k3 = __ldg(kp + e3.x * 32 + lane);
            float p0 = qv.x * k0.x + qv.y * k0.y + qv.z * k0.z + qv.w * k0.w;
            float p1 = qv.x * k1.x + qv.y * k1.y + qv.z * k1.z + qv.w * k1.w;
            float p2 = qv.x * k2.x + qv.y * k2.y + qv.z * k2.z + qv.w * k2.w;
            float p3 = qv.x * k3.x + qv.y * k3.y + qv.z * k3.z + qv.w * k3.w;
#pragma unroll
            for (int off = 8; off >= 1; off >>= 1) {
                p0 += __shfl_xor_sync(0xffffffffu, p0, off);
                p1 += __shfl_xor_sync(0xffffffffu, p1, off);
                p2 += __shfl_xor_sync(0xffffffffu, p2, off);
                p3 += __shfl_xor_sync(0xffffffffu, p3, off);
            }
            if (head_lane) {
                int bidx = pos - s0;
                float v0 = __expf(p0), v1 = __expf(p1);
                float v2 = __expf(p2), v3 = __expf(p3);
                ((float*)&exs[warp][bidx + 0])[h] = v0;
                ((float*)&exs[warp][bidx + 1])[h] = v1;
                ((float*)&exs[warp][bidx + 2])[h] = v2;
                ((float*)&exs[warp][bidx + 3])[h] = v3;
                d += (v0 + v1) + (v2 + v3);
            }
        }
        for (; pos < s1; pos++) {
            int2 e0 = g_sedge[pos];
            float4 k0 = __ldg(kp + e0.x * 32 + lane);
            float p0 = qv.x * k0.x + qv.y * k0.y + qv.z * k0.z + qv.w * k0.w;
#pragma unroll
            for (int off = 8; off >= 1; off >>= 1)
                p0 += __shfl_xor_sync(0xffffffffu, p0, off);
            if (head_lane) {
                float v0 = __expf(p0);
                ((float*)&exs[warp][pos - s0])[h] = v0;
                d += v0;
            }
        }
        float D0 = __shfl_sync(0xffffffffu, d, 0);
        float D1 = __shfl_sync(0xffffffffu, d, 16);
        float i0 = 0.5f / D0, i1 = 0.5f / D1;
        __syncwarp();
        for (int j = lane; j < deg; j += 32) {
            float2 e = exs[warp][j];
            out[g_sedge[s0 + j].y] = e.x * i0 + e.y * i1;
        }
    } else {
        // fallback: exp values through global scratch (rare: deg > 128)
        for (int pos = s0; pos < s1; pos++) {
            int2 e0 = g_sedge[pos];
            float4 k0 = __ldg(kp + e0.x * 32 + lane);
            float p0 = qv.x * k0.x + qv.y * k0.y + qv.z * k0.z + qv.w * k0.w;
#pragma unroll
            for (int off = 8; off >= 1; off >>= 1)
                p0 += __shfl_xor_sync(0xffffffffu, p0, off);
            if (head_lane) {
                float v0 = __expf(p0);
                g_ex2[2 * (size_t)pos + h] = v0;
                d += v0;
            }
        }
        float D0 = __shfl_sync(0xffffffffu, d, 0);
        float D1 = __shfl_sync(0xffffffffu, d, 16);
        float i0 = 0.5f / D0, i1 = 0.5f / D1;
        __syncwarp();
        for (int j = lane; j < deg; j += 32) {
            float2 e = *(const float2*)(g_ex2 + 2 * (size_t)(s0 + j));
            out[g_sedge[s0 + j].y] = e.x * i0 + e.y * i1;
        }
    }
}

extern "C" void kernel_launch(void* const* d_in, const int* in_sizes, int n_in,
                              void* d_out, int out_size) {
    const float* x    = (const float*)d_in[0];
    const float* W_qk = (const float*)d_in[1];
    const float* b_qk = (const float*)d_in[2];
    const int*   ei   = (const int*)d_in[3];   // [2, E] row-major
    const int* row = ei;
    const int* col = ei + EE;
    float* out = (float*)d_out;

    hist_kernel<<<(EE / 4 + 255) / 256, 256>>>((const int4*)row);
    scan1_kernel<<<SCAN_BLOCKS, 256>>>();
    scan3b_kernel<<<SCAN_BLOCKS, 256>>>();
    scatter_kernel<<<(EE + 255) / 256, 256>>>(row, col);
    gemm_qk_kernel<<<(NN + 63) / 64, 256>>>(x, W_qk, b_qk);
    edge_row_kernel<<<(NN + 7) / 8, 256>>>(out);
}